// round 1
// baseline (speedup 1.0000x reference)
#include <cuda_runtime.h>
#include <math.h>
#include <stdint.h>

#define HID 512
#define BSZ 64
#define TLEN 128
#define VOC 32000
#define G3H 1536

// ---------------- scratch (__device__ globals; no allocations allowed) ----
__device__ float g_gi[TLEN * G3H * BSZ];   // giT[t][j][b]  (encoder input gates, 50.3MB)
__device__ float g_hA[HID * BSZ];          // hT[k][b] ping
__device__ float g_hB[HID * BSZ];          // hT[k][b] pong
__device__ float g_eT[HID * BSZ];          // decoder input embedding, transposed
__device__ int   g_tok[BSZ];
__device__ unsigned long long g_amax[BSZ];

__device__ __forceinline__ unsigned ordered_f32(float f) {
    unsigned u = __float_as_uint(f);
    return (u & 0x80000000u) ? ~u : (u | 0x80000000u);
}

// ---------------- init ----------------------------------------------------
__global__ void k_init() {
    int idx = blockIdx.x * blockDim.x + threadIdx.x;
    if (idx < HID * BSZ) { g_hA[idx] = 0.f; }
    if (idx < BSZ) { g_tok[idx] = 2; g_amax[idx] = 0ull; }
}

// ---------------- SGEMM: C[m,n] = sum_k A[m,k]*W[n,k] + bias[n] -----------
// MODE 0: A gathered from embedding table via tokens; epilogue stores
//         transposed into g_gi[t][n][b] (one t per m-tile, BM==BSZ==64).
// MODE 1: A = hT (k-major, [512][64]); epilogue stores logits row-major to
//         `out`, plus packed-key atomicMax argmax into g_amax.
template<int MODE>
__global__ void __launch_bounds__(256) sgemm_k(
    const float* __restrict__ Asrc, const int* __restrict__ tokens,
    const float* __restrict__ W, const float* __restrict__ bias,
    float* __restrict__ out, int hsel)
{
    __shared__ float As[32][68];
    __shared__ float Bs[32][132];
    const int tid = threadIdx.x;
    const int tx = tid & 15, ty = tid >> 4;
    const int nblk = blockIdx.x * 128;
    const int mblk = blockIdx.y * 64;

    const int c4a = tid & 7, rowa = tid >> 3;   // MODE0 A-load mapping
    const int c4m = tid & 15, ka   = tid >> 4;  // MODE1 A-load mapping
    const int c4b = tid & 7, rowb = tid >> 3;   // B-load mapping

    const float* Ak = Asrc;
    int grow0 = 0, grow1 = 0;
    if (MODE == 0) {
        grow0 = tokens[mblk + rowa];
        grow1 = tokens[mblk + rowa + 32];
    } else {
        Ak = hsel ? g_hB : g_hA;
    }
    const float* Wb = W + (size_t)nblk * HID;

    float acc[4][8];
#pragma unroll
    for (int i = 0; i < 4; i++)
#pragma unroll
        for (int j = 0; j < 8; j++) acc[i][j] = 0.f;

    float4 aR0, aR1, bR0, bR1, bR2, bR3;

#define LDG_TILE(k0) do {                                                     \
    if (MODE == 0) {                                                          \
        aR0 = *(const float4*)(Ak + (size_t)grow0 * HID + (k0) + c4a * 4);    \
        aR1 = *(const float4*)(Ak + (size_t)grow1 * HID + (k0) + c4a * 4);    \
    } else {                                                                  \
        aR0 = *(const float4*)(Ak + (size_t)((k0) + ka)      * 64 + c4m * 4); \
        aR1 = *(const float4*)(Ak + (size_t)((k0) + ka + 16) * 64 + c4m * 4); \
    }                                                                         \
    bR0 = *(const float4*)(Wb + (size_t)(rowb      ) * HID + (k0) + c4b * 4); \
    bR1 = *(const float4*)(Wb + (size_t)(rowb +  32) * HID + (k0) + c4b * 4); \
    bR2 = *(const float4*)(Wb + (size_t)(rowb +  64) * HID + (k0) + c4b * 4); \
    bR3 = *(const float4*)(Wb + (size_t)(rowb +  96) * HID + (k0) + c4b * 4); \
} while (0)

#define STS_TILE() do {                                                       \
    if (MODE == 0) {                                                          \
        As[c4a*4+0][rowa] = aR0.x; As[c4a*4+1][rowa] = aR0.y;                 \
        As[c4a*4+2][rowa] = aR0.z; As[c4a*4+3][rowa] = aR0.w;                 \
        As[c4a*4+0][rowa+32] = aR1.x; As[c4a*4+1][rowa+32] = aR1.y;           \
        As[c4a*4+2][rowa+32] = aR1.z; As[c4a*4+3][rowa+32] = aR1.w;           \
    } else {                                                                  \
        *(float4*)&As[ka     ][c4m*4] = aR0;                                  \
        *(float4*)&As[ka + 16][c4m*4] = aR1;                                  \
    }                                                                         \
    Bs[c4b*4+0][rowb   ] = bR0.x; Bs[c4b*4+1][rowb   ] = bR0.y;               \
    Bs[c4b*4+2][rowb   ] = bR0.z; Bs[c4b*4+3][rowb   ] = bR0.w;               \
    Bs[c4b*4+0][rowb+32] = bR1.x; Bs[c4b*4+1][rowb+32] = bR1.y;               \
    Bs[c4b*4+2][rowb+32] = bR1.z; Bs[c4b*4+3][rowb+32] = bR1.w;               \
    Bs[c4b*4+0][rowb+64] = bR2.x; Bs[c4b*4+1][rowb+64] = bR2.y;               \
    Bs[c4b*4+2][rowb+64] = bR2.z; Bs[c4b*4+3][rowb+64] = bR2.w;               \
    Bs[c4b*4+0][rowb+96] = bR3.x; Bs[c4b*4+1][rowb+96] = bR3.y;               \
    Bs[c4b*4+2][rowb+96] = bR3.z; Bs[c4b*4+3][rowb+96] = bR3.w;               \
} while (0)

    LDG_TILE(0);
#pragma unroll 1
    for (int kt = 0; kt < 16; kt++) {
        __syncthreads();
        STS_TILE();
        __syncthreads();
        if (kt < 15) { LDG_TILE((kt + 1) * 32); }
#pragma unroll
        for (int k = 0; k < 32; k++) {
            float4 a  = *(const float4*)&As[k][ty * 4];
            float4 b0 = *(const float4*)&Bs[k][tx * 4];
            float4 b1 = *(const float4*)&Bs[k][64 + tx * 4];
            float av[4] = {a.x, a.y, a.z, a.w};
            float bv[8] = {b0.x, b0.y, b0.z, b0.w, b1.x, b1.y, b1.z, b1.w};
#pragma unroll
            for (int i = 0; i < 4; i++)
#pragma unroll
                for (int j = 0; j < 8; j++)
                    acc[i][j] = fmaf(av[i], bv[j], acc[i][j]);
        }
    }
#undef LDG_TILE
#undef STS_TILE

    if (MODE == 0) {
        // store transposed with bias: g_gi[(t*G3H + n)*64 + m]
        const int t = blockIdx.y;
        float* gout = g_gi + ((size_t)t * G3H + nblk) * 64;
#pragma unroll
        for (int j = 0; j < 8; j++) {
            int nl = (j < 4) ? (tx * 4 + j) : (64 + tx * 4 + (j - 4));
            float bb = bias[nblk + nl];
            float4 v = make_float4(acc[0][j] + bb, acc[1][j] + bb,
                                   acc[2][j] + bb, acc[3][j] + bb);
            *(float4*)(gout + (size_t)nl * 64 + ty * 4) = v;
        }
    } else {
        // logits: row-major store + argmax atomics
#pragma unroll
        for (int i = 0; i < 4; i++) {
            int b = ty * 4 + i;
            float* orow = out + (size_t)b * VOC + nblk;
            float v[8];
            float best = -3.4e38f;
            int bestn = 0;
#pragma unroll
            for (int j = 0; j < 8; j++) {
                int nl = (j < 4) ? (tx * 4 + j) : (64 + tx * 4 + (j - 4));
                v[j] = acc[i][j] + bias[nblk + nl];
                if (v[j] > best) { best = v[j]; bestn = nblk + nl; }
            }
            *(float4*)(orow + tx * 4)      = make_float4(v[0], v[1], v[2], v[3]);
            *(float4*)(orow + 64 + tx * 4) = make_float4(v[4], v[5], v[6], v[7]);
            unsigned long long key =
                ((unsigned long long)ordered_f32(best) << 32) |
                (unsigned long long)(0xFFFFFFFFu - (unsigned)bestn);
            atomicMax(&g_amax[b], key);
        }
    }
}

// ---------------- fused GRU gate step -------------------------------------
// ENC (DEC=0): 128 CTAs x 256 thr, 4 hidden units/CTA; gi read from g_gi[t].
// DEC (DEC=1): 256 CTAs x 128 thr, 2 hidden units/CTA; gi computed from
//              g_eT and Wih_d in the same pass (6 dot products/thread).
template<int DEC>
__global__ void gru_gate_k(
    const float* __restrict__ Wih, const float* __restrict__ bih,
    const float* __restrict__ Whh, const float* __restrict__ bhh,
    const int* __restrict__ lengths, int t, int par)
{
    constexpr int UPB = DEC ? 2 : 4;
    __shared__ float Wh[3 * UPB][HID];
    __shared__ float Wi[DEC ? 3 * UPB : 1][HID];
    const int tid = threadIdx.x;
    const int u0 = blockIdx.x * UPB;
    const int nth = 64 * UPB;

    for (int idx = tid; idx < 3 * UPB * HID; idx += nth) {
        int r = idx >> 9, k = idx & 511;
        int g = r / UPB, ui = r % UPB;
        size_t wrow = (size_t)(g * HID + u0 + ui) * HID;
        Wh[r][k] = Whh[wrow + k];
        if (DEC) Wi[r][k] = Wih[wrow + k];
    }
    __syncthreads();

    const float* hin = par ? g_hB : g_hA;
    float* hout = par ? g_hA : g_hB;
    const int b = tid & 63;
    const int ui = tid >> 6;
    const int u = u0 + ui;

    float aR = bhh[u], aZ = bhh[HID + u], aN = bhh[2 * HID + u];
    float iR, iZ, iN;
    if (DEC) {
        iR = bih[u]; iZ = bih[HID + u]; iN = bih[2 * HID + u];
    } else {
        const float* gi = g_gi + (size_t)t * (G3H * 64);
        iR = gi[(size_t)u * 64 + b];
        iZ = gi[(size_t)(HID + u) * 64 + b];
        iN = gi[(size_t)(2 * HID + u) * 64 + b];
    }

    for (int k0 = 0; k0 < HID; k0 += 8) {
        float hv[8];
#pragma unroll
        for (int kk = 0; kk < 8; kk++)
            hv[kk] = __ldg(hin + (size_t)(k0 + kk) * 64 + b);
        const float* wr = &Wh[ui][k0];
        const float* wz = &Wh[UPB + ui][k0];
        const float* wn = &Wh[2 * UPB + ui][k0];
#pragma unroll
        for (int kk = 0; kk < 8; kk++) {
            aR = fmaf(hv[kk], wr[kk], aR);
            aZ = fmaf(hv[kk], wz[kk], aZ);
            aN = fmaf(hv[kk], wn[kk], aN);
        }
        if (DEC) {
            float ev[8];
#pragma unroll
            for (int kk = 0; kk < 8; kk++)
                ev[kk] = __ldg(g_eT + (size_t)(k0 + kk) * 64 + b);
            const float* vr = &Wi[ui][k0];
            const float* vz = &Wi[UPB + ui][k0];
            const float* vn = &Wi[2 * UPB + ui][k0];
#pragma unroll
            for (int kk = 0; kk < 8; kk++) {
                iR = fmaf(ev[kk], vr[kk], iR);
                iZ = fmaf(ev[kk], vz[kk], iZ);
                iN = fmaf(ev[kk], vn[kk], iN);
            }
        }
    }

    float r = 1.f / (1.f + expf(-(iR + aR)));
    float z = 1.f / (1.f + expf(-(iZ + aZ)));
    float n = tanhf(iN + r * aN);
    float hp = hin[(size_t)u * 64 + b];
    float hn = (1.f - z) * n + z * hp;
    if (!DEC) hn = (t < lengths[b]) ? hn : hp;   // packed-sequence freeze
    hout[(size_t)u * 64 + b] = hn;
}

// ---------------- decoder embedding gather (transposed) -------------------
__global__ void k_egather(const float* __restrict__ emb_dec) {
    int b = blockIdx.x;
    int row = g_tok[b];
    const float* src = emb_dec + (size_t)row * HID;
    for (int k = threadIdx.x; k < HID; k += blockDim.x)
        g_eT[(size_t)k * 64 + b] = src[k];
}

// ---------------- argmax finalize ----------------------------------------
__global__ void k_fin() {
    int b = threadIdx.x;
    if (b < BSZ) {
        unsigned long long key = g_amax[b];
        g_tok[b] = (int)(0xFFFFFFFFu - (unsigned)(key & 0xFFFFFFFFull));
        g_amax[b] = 0ull;
    }
}

// ---------------- host orchestration --------------------------------------
extern "C" void kernel_launch(void* const* d_in, const int* in_sizes, int n_in,
                              void* d_out, int out_size) {
    const int*   batch_X = (const int*)d_in[0];
    const int*   lengths = (const int*)d_in[1];
    // d_in[2] = max_length (derived from out_size instead)
    const float* emb_enc = (const float*)d_in[3];
    const float* Wih_e   = (const float*)d_in[4];
    const float* Whh_e   = (const float*)d_in[5];
    const float* bih_e   = (const float*)d_in[6];
    const float* bhh_e   = (const float*)d_in[7];
    const float* emb_dec = (const float*)d_in[8];
    const float* Wih_d   = (const float*)d_in[9];
    const float* Whh_d   = (const float*)d_in[10];
    const float* bih_d   = (const float*)d_in[11];
    const float* bhh_d   = (const float*)d_in[12];
    const float* Wout    = (const float*)d_in[13];
    const float* bout    = (const float*)d_in[14];
    float* out = (float*)d_out;
    const int steps = out_size / (BSZ * VOC);   // 32

    (void)in_sizes; (void)n_in;

    k_init<<<128, 256>>>();

    // encoder input pre-GEMM: all timesteps at once (8192 x 1536, K=512)
    sgemm_k<0><<<dim3(G3H / 128, (TLEN * BSZ) / 64), 256>>>(
        emb_enc, batch_X, Wih_e, bih_e, nullptr, 0);

    // encoder recurrence
    for (int t = 0; t < TLEN; t++)
        gru_gate_k<0><<<HID / 4, 256>>>(nullptr, nullptr, Whh_e, bhh_e,
                                        lengths, t, t & 1);
    // final hidden ends in g_hA (128 steps, even)

    // decoder greedy loop
    for (int s = 0; s < steps; s++) {
        k_egather<<<BSZ, 128>>>(emb_dec);
        gru_gate_k<1><<<HID / 2, 128>>>(Wih_d, bih_d, Whh_d, bhh_d,
                                        nullptr, 0, s & 1);
        // h_new lives in the buffer opposite to (s&1): hsel=1 -> g_hB
        sgemm_k<1><<<dim3(VOC / 128, 1), 256>>>(
            nullptr, nullptr, Wout, bout,
            out + (size_t)s * BSZ * VOC, 1 - (s & 1));
        k_fin<<<1, 64>>>();
    }
}